// round 11
// baseline (speedup 1.0000x reference)
#include <cuda_runtime.h>
#include <cuda_bf16.h>
#include <math.h>
#include <cstdint>

#define Nn 50000
#define Ee 800000
#define INF 30
#define Hh 8
#define Dd 32
#define Gg 512
#define HID 128
#define ALPHA 0.2f
#define BN_EPS 1e-5f
#define F (Hh*Dd)   // 256
#define SPLIT 25088  // chunk-A node count (196*128)

// ---------------- helpers ----------------
__device__ __forceinline__ unsigned f2tf32(float f) {
    unsigned u;
    asm("cvt.rna.tf32.f32 %0, %1;" : "=r"(u) : "f"(f));
    return u;
}

__device__ __forceinline__ void atomicMaxFloat(float* addr, float val) {
    int* ia = (int*)addr;
    int old = *ia;
    while (__int_as_float(old) < val) {
        int prev = atomicCAS(ia, old, __float_as_int(val));
        if (prev == old) break;
        old = prev;
    }
}

// ---------------- scratch (allocation-free: __device__ globals) ----------------
__device__ __nv_bfloat16 g_featb [Nn * F];  // layer-1 features (bf16)
__device__ __nv_bfloat16 g_featb2[Nn * F];  // layer-2 features (bf16)
__device__ float g_base[Nn * F];     // layer1: b1 + x@resW1
__device__ float g_h1  [Nn * F];     // layer1 activation (fp32)
__device__ float g_el [Nn * Hh];
__device__ float g_er [Nn * Hh];
__device__ float g_el2[Nn * Hh];
__device__ float g_er2[Nn * Hh];
__device__ int   g_cnt [Nn];
__device__ int   g_rowptr[Nn + 1];
__device__ int   g_cursor[Nn];
__device__ int   g_csrc[Ee];
__device__ int   g_bsum[256];
__device__ float g_gsum[Gg * Dd];
__device__ float g_gmax[Gg * Dd];

__global__ void fill_kernel(float* p, int n, float val) {
    int i = blockIdx.x * blockDim.x + threadIdx.x;
    if (i < n) p[i] = val;
}
__global__ void fill_int_kernel(int* p, int n, int val) {
    int i = blockIdx.x * blockDim.x + threadIdx.x;
    if (i < n) p[i] = val;
}

// ---------------- CSR build ----------------
__global__ void hist_kernel(const int* __restrict__ dst) {
    int e = blockIdx.x * blockDim.x + threadIdx.x;
    if (e < Ee) atomicAdd(&g_cnt[dst[e]], 1);
}

__global__ void scan1_kernel() {
    __shared__ int sd[256];
    int t = threadIdx.x;
    int i = blockIdx.x * 256 + t;
    int v = (i < Nn) ? g_cnt[i] : 0;
    sd[t] = v;
    __syncthreads();
    #pragma unroll
    for (int off = 1; off < 256; off <<= 1) {
        int x = (t >= off) ? sd[t - off] : 0;
        __syncthreads();
        sd[t] += x;
        __syncthreads();
    }
    if (i < Nn) g_rowptr[i] = sd[t] - v;
    if (t == 255) g_bsum[blockIdx.x] = sd[255];
}

__global__ void scan2_kernel(int nb) {
    __shared__ int sd[256];
    int t = threadIdx.x;
    int v = (t < nb) ? g_bsum[t] : 0;
    sd[t] = v;
    __syncthreads();
    #pragma unroll
    for (int off = 1; off < 256; off <<= 1) {
        int x = (t >= off) ? sd[t - off] : 0;
        __syncthreads();
        sd[t] += x;
        __syncthreads();
    }
    if (t < nb) g_bsum[t] = sd[t] - v;
    if (t == 0) g_rowptr[Nn] = Ee;
}

__global__ void scan3_kernel() {
    int i = blockIdx.x * 256 + threadIdx.x;
    if (i < Nn) {
        int r = g_rowptr[i] + g_bsum[blockIdx.x];
        g_rowptr[i] = r;
        g_cursor[i] = r;
    }
}

__global__ void scatter_kernel(const int* __restrict__ src, const int* __restrict__ dst) {
    int e = blockIdx.x * blockDim.x + threadIdx.x;
    if (e >= Ee) return;
    int d = dst[e];
    int pos = atomicAdd(&g_cursor[d], 1);
    g_csrc[pos] = src[e];
}

// ================= layer-1 tensor-core projection =================
__global__ void node1_tc_kernel(const float* __restrict__ x,
                                const float* __restrict__ W1,
                                const float* __restrict__ resW1,
                                const float* __restrict__ b1,
                                const float* __restrict__ al1,
                                const float* __restrict__ ar1) {
    __shared__ float As[128][36];
    __shared__ float Bs[32][132];
    int tid = threadIdx.x;
    int lane = tid & 31, warp = tid >> 5;
    int g = lane >> 2, tig = lane & 3;
    int mw = (warp & 1) * 64;
    int nw = (warp >> 1) * 32;
    int rowBase = blockIdx.y * 128;
    int colBase = blockIdx.x * 128;     // 0,128 = feat; 256,384 = residual

    #pragma unroll
    for (int i = 0; i < 16; i++) {
        int id = tid + i * 256;
        int r = id >> 5, c = id & 31;
        int gr = rowBase + r;
        float v = (gr < Nn && c < INF) ? x[gr * INF + c] : 0.f;
        As[r][c] = __uint_as_float(f2tf32(v));
    }
    #pragma unroll
    for (int i = 0; i < 16; i++) {
        int id = tid + i * 256;
        int r = id >> 7, c = id & 127;
        int j = colBase + c;
        float v = 0.f;
        if (r < INF) v = (j < 256) ? W1[r * 256 + j] : resW1[r * 256 + (j - 256)];
        Bs[r][c] = __uint_as_float(f2tf32(v));
    }
    __syncthreads();

    float cf[4][4][4];
    #pragma unroll
    for (int mt = 0; mt < 4; mt++)
        #pragma unroll
        for (int nt = 0; nt < 4; nt++)
            #pragma unroll
            for (int q = 0; q < 4; q++) cf[mt][nt][q] = 0.f;

    #pragma unroll
    for (int k8 = 0; k8 < 32; k8 += 8) {
        unsigned a[4][4], b[4][2];
        #pragma unroll
        for (int mt = 0; mt < 4; mt++) {
            int r0 = mw + mt * 16;
            a[mt][0] = __float_as_uint(As[r0 + g][k8 + tig]);
            a[mt][1] = __float_as_uint(As[r0 + g + 8][k8 + tig]);
            a[mt][2] = __float_as_uint(As[r0 + g][k8 + tig + 4]);
            a[mt][3] = __float_as_uint(As[r0 + g + 8][k8 + tig + 4]);
        }
        #pragma unroll
        for (int nt = 0; nt < 4; nt++) {
            int cn = nw + nt * 8;
            b[nt][0] = __float_as_uint(Bs[k8 + tig][cn + g]);
            b[nt][1] = __float_as_uint(Bs[k8 + tig + 4][cn + g]);
        }
        #pragma unroll
        for (int mt = 0; mt < 4; mt++)
            #pragma unroll
            for (int nt = 0; nt < 4; nt++)
                asm volatile(
                    "mma.sync.aligned.m16n8k8.row.col.f32.tf32.tf32.f32 "
                    "{%0,%1,%2,%3},{%4,%5,%6,%7},{%8,%9},{%0,%1,%2,%3};"
                    : "+f"(cf[mt][nt][0]), "+f"(cf[mt][nt][1]),
                      "+f"(cf[mt][nt][2]), "+f"(cf[mt][nt][3])
                    : "r"(a[mt][0]), "r"(a[mt][1]), "r"(a[mt][2]), "r"(a[mt][3]),
                      "r"(b[nt][0]), "r"(b[nt][1]));
    }

    if (colBase < 256) {
        #pragma unroll
        for (int mt = 0; mt < 4; mt++) {
            int gr0 = rowBase + mw + mt * 16 + g;
            int gr1 = gr0 + 8;
            #pragma unroll
            for (int nt = 0; nt < 4; nt++) {
                int col = colBase + nw + nt * 8 + tig * 2;
                if (gr0 < Nn) {
                    __nv_bfloat162 p = __floats2bfloat162_rn(cf[mt][nt][0], cf[mt][nt][1]);
                    *(__nv_bfloat162*)&g_featb[gr0 * F + col] = p;
                }
                if (gr1 < Nn) {
                    __nv_bfloat162 p = __floats2bfloat162_rn(cf[mt][nt][2], cf[mt][nt][3]);
                    *(__nv_bfloat162*)&g_featb[gr1 * F + col] = p;
                }
            }
        }
        int hid = (colBase + nw) >> 5;
        float alv[4][2], arv[4][2];
        #pragma unroll
        for (int nt = 0; nt < 4; nt++) {
            int col = colBase + nw + nt * 8 + tig * 2;
            alv[nt][0] = al1[col]; alv[nt][1] = al1[col + 1];
            arv[nt][0] = ar1[col]; arv[nt][1] = ar1[col + 1];
        }
        #pragma unroll
        for (int mt = 0; mt < 4; mt++) {
            float el0 = 0.f, el1v = 0.f, er0 = 0.f, er1v = 0.f;
            #pragma unroll
            for (int nt = 0; nt < 4; nt++) {
                el0  += cf[mt][nt][0] * alv[nt][0] + cf[mt][nt][1] * alv[nt][1];
                el1v += cf[mt][nt][2] * alv[nt][0] + cf[mt][nt][3] * alv[nt][1];
                er0  += cf[mt][nt][0] * arv[nt][0] + cf[mt][nt][1] * arv[nt][1];
                er1v += cf[mt][nt][2] * arv[nt][0] + cf[mt][nt][3] * arv[nt][1];
            }
            el0  += __shfl_xor_sync(0xffffffffu, el0, 1);  el0  += __shfl_xor_sync(0xffffffffu, el0, 2);
            el1v += __shfl_xor_sync(0xffffffffu, el1v, 1); el1v += __shfl_xor_sync(0xffffffffu, el1v, 2);
            er0  += __shfl_xor_sync(0xffffffffu, er0, 1);  er0  += __shfl_xor_sync(0xffffffffu, er0, 2);
            er1v += __shfl_xor_sync(0xffffffffu, er1v, 1); er1v += __shfl_xor_sync(0xffffffffu, er1v, 2);
            if (tig == 0) {
                int gr0 = rowBase + mw + mt * 16 + g;
                int gr1 = gr0 + 8;
                if (gr0 < Nn) { g_el[gr0 * Hh + hid] = el0;  g_er[gr0 * Hh + hid] = er0; }
                if (gr1 < Nn) { g_el[gr1 * Hh + hid] = el1v; g_er[gr1 * Hh + hid] = er1v; }
            }
        }
    } else {
        #pragma unroll
        for (int mt = 0; mt < 4; mt++) {
            int gr0 = rowBase + mw + mt * 16 + g;
            int gr1 = gr0 + 8;
            #pragma unroll
            for (int nt = 0; nt < 4; nt++) {
                int j = colBase - 256 + nw + nt * 8 + tig * 2;
                float bj0 = b1[j], bj1 = b1[j + 1];
                if (gr0 < Nn) {
                    float2 v = make_float2(cf[mt][nt][0] + bj0, cf[mt][nt][1] + bj1);
                    *(float2*)&g_base[gr0 * F + j] = v;
                }
                if (gr1 < Nn) {
                    float2 v = make_float2(cf[mt][nt][2] + bj0, cf[mt][nt][3] + bj1);
                    *(float2*)&g_base[gr1 * F + j] = v;
                }
            }
        }
    }
}

// ---------------- layer 1: warp-per-node fused softmax + gather + ELU (node range) ----------------
__global__ void agg1_kernel(int nodeOff) {
    int n = nodeOff + (blockIdx.x << 3) + (threadIdx.x >> 5);
    if (n >= Nn) return;
    int lane = threadIdx.x & 31;
    int h = lane >> 2;
    float er_h = g_er[n * Hh + h];
    int start = g_rowptr[n];
    int deg = g_rowptr[n + 1] - start;

    float a0=0.f,a1=0.f,a2=0.f,a3=0.f,a4=0.f,a5=0.f,a6=0.f,a7=0.f;
    float ssum = 0.f;
    for (int c0 = 0; c0 < deg; c0 += 32) {
        int idx = c0 + lane;
        int s_l = (idx < deg) ? g_csrc[start + idx] : 0;
        int cnt = min(32, deg - c0);
        #pragma unroll 4
        for (int q = 0; q < cnt; q++) {
            int s = __shfl_sync(0xffffffffu, s_l, q);
            float v = g_el[s * Hh + h] + er_h;
            v = v > 0.f ? v : ALPHA * v;
            float ex = __expf(v);
            ssum += ex;
            uint4 u = *(const uint4*)&g_featb[s * F + lane * 8];
            float2 f0 = __bfloat1622float2(*(const __nv_bfloat162*)&u.x);
            float2 f1 = __bfloat1622float2(*(const __nv_bfloat162*)&u.y);
            float2 f2 = __bfloat1622float2(*(const __nv_bfloat162*)&u.z);
            float2 f3 = __bfloat1622float2(*(const __nv_bfloat162*)&u.w);
            a0 = fmaf(ex, f0.x, a0); a1 = fmaf(ex, f0.y, a1);
            a2 = fmaf(ex, f1.x, a2); a3 = fmaf(ex, f1.y, a3);
            a4 = fmaf(ex, f2.x, a4); a5 = fmaf(ex, f2.y, a5);
            a6 = fmaf(ex, f3.x, a6); a7 = fmaf(ex, f3.y, a7);
        }
    }
    float inv = 1.f / fmaxf(ssum, 1e-9f);

    float4 b0 = *(const float4*)&g_base[n * F + lane * 8];
    float4 b1v = *(const float4*)&g_base[n * F + lane * 8 + 4];
    float r0 = b0.x + a0 * inv, r1 = b0.y + a1 * inv;
    float r2 = b0.z + a2 * inv, r3 = b0.w + a3 * inv;
    float r4 = b1v.x + a4 * inv, r5 = b1v.y + a5 * inv;
    float r6 = b1v.z + a6 * inv, r7 = b1v.w + a7 * inv;
    r0 = r0 > 0.f ? r0 : (__expf(r0) - 1.f);
    r1 = r1 > 0.f ? r1 : (__expf(r1) - 1.f);
    r2 = r2 > 0.f ? r2 : (__expf(r2) - 1.f);
    r3 = r3 > 0.f ? r3 : (__expf(r3) - 1.f);
    r4 = r4 > 0.f ? r4 : (__expf(r4) - 1.f);
    r5 = r5 > 0.f ? r5 : (__expf(r5) - 1.f);
    r6 = r6 > 0.f ? r6 : (__expf(r6) - 1.f);
    r7 = r7 > 0.f ? r7 : (__expf(r7) - 1.f);
    *(float4*)&g_h1[n * F + lane * 8]     = make_float4(r0, r1, r2, r3);
    *(float4*)&g_h1[n * F + lane * 8 + 4] = make_float4(r4, r5, r6, r7);
}

// ---------------- layer 2: warp-per-node fused agg + head-mean + gated readout ----------------
__global__ void agg2_kernel(const float* __restrict__ b2,
                            const int* __restrict__ graph_ids,
                            const float* __restrict__ Ww,
                            const float* __restrict__ bw) {
    int n = (blockIdx.x << 3) + (threadIdx.x >> 5);
    int lane = threadIdx.x & 31;
    int h = lane >> 2;
    float er_h = g_er2[n * Hh + h];
    int start = g_rowptr[n];
    int deg = g_rowptr[n + 1] - start;

    float a0=0.f,a1=0.f,a2=0.f,a3=0.f,a4=0.f,a5=0.f,a6=0.f,a7=0.f;
    float ssum = 0.f;
    for (int c0 = 0; c0 < deg; c0 += 32) {
        int idx = c0 + lane;
        int s_l = (idx < deg) ? g_csrc[start + idx] : 0;
        int cnt = min(32, deg - c0);
        #pragma unroll 4
        for (int q = 0; q < cnt; q++) {
            int s = __shfl_sync(0xffffffffu, s_l, q);
            float v = g_el2[s * Hh + h] + er_h;
            v = v > 0.f ? v : ALPHA * v;
            float ex = __expf(v);
            ssum += ex;
            uint4 u = *(const uint4*)&g_featb2[s * F + lane * 8];
            float2 f0 = __bfloat1622float2(*(const __nv_bfloat162*)&u.x);
            float2 f1 = __bfloat1622float2(*(const __nv_bfloat162*)&u.y);
            float2 f2 = __bfloat1622float2(*(const __nv_bfloat162*)&u.z);
            float2 f3 = __bfloat1622float2(*(const __nv_bfloat162*)&u.w);
            a0 = fmaf(ex, f0.x, a0); a1 = fmaf(ex, f0.y, a1);
            a2 = fmaf(ex, f1.x, a2); a3 = fmaf(ex, f1.y, a3);
            a4 = fmaf(ex, f2.x, a4); a5 = fmaf(ex, f2.y, a5);
            a6 = fmaf(ex, f3.x, a6); a7 = fmaf(ex, f3.y, a7);
        }
    }
    float inv = 1.f / fmaxf(ssum, 1e-9f);

    float4 h0v = *(const float4*)&g_h1[n * F + lane * 8];
    float4 h1v = *(const float4*)&g_h1[n * F + lane * 8 + 4];
    float4 bb0 = *(const float4*)&b2[lane * 8];
    float4 bb1 = *(const float4*)&b2[lane * 8 + 4];
    float r0 = h0v.x + bb0.x + a0 * inv, r1 = h0v.y + bb0.y + a1 * inv;
    float r2 = h0v.z + bb0.z + a2 * inv, r3 = h0v.w + bb0.w + a3 * inv;
    float r4 = h1v.x + bb1.x + a4 * inv, r5 = h1v.y + bb1.y + a5 * inv;
    float r6 = h1v.z + bb1.z + a6 * inv, r7 = h1v.w + bb1.w + a7 * inv;

    #pragma unroll
    for (int o = 4; o <= 16; o <<= 1) {
        r0 += __shfl_xor_sync(0xffffffffu, r0, o);
        r1 += __shfl_xor_sync(0xffffffffu, r1, o);
        r2 += __shfl_xor_sync(0xffffffffu, r2, o);
        r3 += __shfl_xor_sync(0xffffffffu, r3, o);
        r4 += __shfl_xor_sync(0xffffffffu, r4, o);
        r5 += __shfl_xor_sync(0xffffffffu, r5, o);
        r6 += __shfl_xor_sync(0xffffffffu, r6, o);
        r7 += __shfl_xor_sync(0xffffffffu, r7, o);
    }
    r0 *= 0.125f; r1 *= 0.125f; r2 *= 0.125f; r3 *= 0.125f;
    r4 *= 0.125f; r5 *= 0.125f; r6 *= 0.125f; r7 *= 0.125f;

    float partial = 0.f;
    if (lane < 4) {
        float4 w0 = *(const float4*)&Ww[lane * 8];
        float4 w1 = *(const float4*)&Ww[lane * 8 + 4];
        partial = r0 * w0.x + r1 * w0.y + r2 * w0.z + r3 * w0.w
                + r4 * w1.x + r5 * w1.y + r6 * w1.z + r7 * w1.w;
    }
    partial += __shfl_xor_sync(0xffffffffu, partial, 1);
    partial += __shfl_xor_sync(0xffffffffu, partial, 2);
    float w = 0.f;
    if (lane == 0) w = 1.f / (1.f + __expf(-(partial + bw[0])));
    w = __shfl_sync(0xffffffffu, w, 0);

    if (lane < 4) {
        int gid = graph_ids[n];
        float* gs = &g_gsum[gid * Dd + lane * 8];
        float* gm = &g_gmax[gid * Dd + lane * 8];
        atomicAdd(gs + 0, w * r0); atomicMaxFloat(gm + 0, r0);
        atomicAdd(gs + 1, w * r1); atomicMaxFloat(gm + 1, r1);
        atomicAdd(gs + 2, w * r2); atomicMaxFloat(gm + 2, r2);
        atomicAdd(gs + 3, w * r3); atomicMaxFloat(gm + 3, r3);
        atomicAdd(gs + 4, w * r4); atomicMaxFloat(gm + 4, r4);
        atomicAdd(gs + 5, w * r5); atomicMaxFloat(gm + 5, r5);
        atomicAdd(gs + 6, w * r6); atomicMaxFloat(gm + 6, r6);
        atomicAdd(gs + 7, w * r7); atomicMaxFloat(gm + 7, r7);
    }
}

// ======= layer-2 tf32 GEMM (row range): featb2=bf16(h1@W2) + el2/er2 epilogue =======
#define TBM 128
#define TBN 128
#define TBK 32
__global__ void gemm2_tc_kernel(const float* __restrict__ A, const float* __restrict__ B,
                                const float* __restrict__ al2, const float* __restrict__ ar2,
                                int rowOff) {
    __shared__ float As[TBM][TBK + 4];
    __shared__ float Bs[TBK][TBN + 4];
    int tid = threadIdx.x;
    int lane = tid & 31, warp = tid >> 5;
    int g = lane >> 2, tig = lane & 3;
    int mw = (warp & 1) * 64;
    int nw = (warp >> 1) * 32;
    int rowBase = rowOff + blockIdx.y * TBM;
    int colBase = blockIdx.x * TBN;

    float cf[4][4][4];
    #pragma unroll
    for (int mt = 0; mt < 4; mt++)
        #pragma unroll
        for (int nt = 0; nt < 4; nt++)
            #pragma unroll
            for (int q = 0; q < 4; q++) cf[mt][nt][q] = 0.f;

    for (int k0 = 0; k0 < F; k0 += TBK) {
        #pragma unroll
        for (int i = 0; i < 4; i++) {
            int id = tid + i * 256;
            int r = id >> 3, c4 = (id & 7) * 4;
            int gr = rowBase + r;
            float4 v = (gr < Nn) ? *(const float4*)&A[gr * F + k0 + c4]
                                 : make_float4(0.f, 0.f, 0.f, 0.f);
            uint4 u;
            u.x = f2tf32(v.x); u.y = f2tf32(v.y); u.z = f2tf32(v.z); u.w = f2tf32(v.w);
            *(uint4*)&As[r][c4] = u;
        }
        #pragma unroll
        for (int i = 0; i < 4; i++) {
            int id = tid + i * 256;
            int r = id >> 5, c4 = (id & 31) * 4;
            float4 v = *(const float4*)&B[(k0 + r) * F + colBase + c4];
            uint4 u;
            u.x = f2tf32(v.x); u.y = f2tf32(v.y); u.z = f2tf32(v.z); u.w = f2tf32(v.w);
            *(uint4*)&Bs[r][c4] = u;
        }
        __syncthreads();
        #pragma unroll
        for (int k8 = 0; k8 < TBK; k8 += 8) {
            unsigned a[4][4], b[4][2];
            #pragma unroll
            for (int mt = 0; mt < 4; mt++) {
                int r0 = mw + mt * 16;
                a[mt][0] = __float_as_uint(As[r0 + g][k8 + tig]);
                a[mt][1] = __float_as_uint(As[r0 + g + 8][k8 + tig]);
                a[mt][2] = __float_as_uint(As[r0 + g][k8 + tig + 4]);
                a[mt][3] = __float_as_uint(As[r0 + g + 8][k8 + tig + 4]);
            }
            #pragma unroll
            for (int nt = 0; nt < 4; nt++) {
                int cn = nw + nt * 8;
                b[nt][0] = __float_as_uint(Bs[k8 + tig][cn + g]);
                b[nt][1] = __float_as_uint(Bs[k8 + tig + 4][cn + g]);
            }
            #pragma unroll
            for (int mt = 0; mt < 4; mt++)
                #pragma unroll
                for (int nt = 0; nt < 4; nt++)
                    asm volatile(
                        "mma.sync.aligned.m16n8k8.row.col.f32.tf32.tf32.f32 "
                        "{%0,%1,%2,%3},{%4,%5,%6,%7},{%8,%9},{%0,%1,%2,%3};"
                        : "+f"(cf[mt][nt][0]), "+f"(cf[mt][nt][1]),
                          "+f"(cf[mt][nt][2]), "+f"(cf[mt][nt][3])
                        : "r"(a[mt][0]), "r"(a[mt][1]), "r"(a[mt][2]), "r"(a[mt][3]),
                          "r"(b[nt][0]), "r"(b[nt][1]));
        }
        __syncthreads();
    }

    #pragma unroll
    for (int mt = 0; mt < 4; mt++) {
        int gr0 = rowBase + mw + mt * 16 + g;
        int gr1 = gr0 + 8;
        #pragma unroll
        for (int nt = 0; nt < 4; nt++) {
            int col = colBase + nw + nt * 8 + tig * 2;
            if (gr0 < Nn) {
                __nv_bfloat162 p = __floats2bfloat162_rn(cf[mt][nt][0], cf[mt][nt][1]);
                *(__nv_bfloat162*)&g_featb2[gr0 * F + col] = p;
            }
            if (gr1 < Nn) {
                __nv_bfloat162 p = __floats2bfloat162_rn(cf[mt][nt][2], cf[mt][nt][3]);
                *(__nv_bfloat162*)&g_featb2[gr1 * F + col] = p;
            }
        }
    }
    int hid = (colBase + nw) >> 5;
    float alv[4][2], arv[4][2];
    #pragma unroll
    for (int nt = 0; nt < 4; nt++) {
        int col = colBase + nw + nt * 8 + tig * 2;
        alv[nt][0] = al2[col]; alv[nt][1] = al2[col + 1];
        arv[nt][0] = ar2[col]; arv[nt][1] = ar2[col + 1];
    }
    #pragma unroll
    for (int mt = 0; mt < 4; mt++) {
        float el0 = 0.f, el1v = 0.f, er0 = 0.f, er1v = 0.f;
        #pragma unroll
        for (int nt = 0; nt < 4; nt++) {
            el0  += cf[mt][nt][0] * alv[nt][0] + cf[mt][nt][1] * alv[nt][1];
            el1v += cf[mt][nt][2] * alv[nt][0] + cf[mt][nt][3] * alv[nt][1];
            er0  += cf[mt][nt][0] * arv[nt][0] + cf[mt][nt][1] * arv[nt][1];
            er1v += cf[mt][nt][2] * arv[nt][0] + cf[mt][nt][3] * arv[nt][1];
        }
        el0  += __shfl_xor_sync(0xffffffffu, el0, 1);  el0  += __shfl_xor_sync(0xffffffffu, el0, 2);
        el1v += __shfl_xor_sync(0xffffffffu, el1v, 1); el1v += __shfl_xor_sync(0xffffffffu, el1v, 2);
        er0  += __shfl_xor_sync(0xffffffffu, er0, 1);  er0  += __shfl_xor_sync(0xffffffffu, er0, 2);
        er1v += __shfl_xor_sync(0xffffffffu, er1v, 1); er1v += __shfl_xor_sync(0xffffffffu, er1v, 2);
        if (tig == 0) {
            int gr0 = rowBase + mw + mt * 16 + g;
            int gr1 = gr0 + 8;
            if (gr0 < Nn) { g_el2[gr0 * Hh + hid] = el0;  g_er2[gr0 * Hh + hid] = er0; }
            if (gr1 < Nn) { g_el2[gr1 * Hh + hid] = el1v; g_er2[gr1 * Hh + hid] = er1v; }
        }
    }
}

// ---------------- MLP head ----------------
__global__ void mlp_kernel(const float* __restrict__ Wp1, const float* __restrict__ bp1,
                           const float* __restrict__ gamma, const float* __restrict__ beta,
                           const float* __restrict__ rm, const float* __restrict__ rv,
                           const float* __restrict__ Wp2, const float* __restrict__ bp2,
                           float* __restrict__ out) {
    int g = blockIdx.x;
    int t = threadIdx.x;      // 0..127
    __shared__ float gv[2 * Dd];
    __shared__ float red[HID];
    if (t < Dd) gv[t] = g_gsum[g * Dd + t];
    else if (t < 2 * Dd) {
        float mv = g_gmax[g * Dd + (t - Dd)];
        gv[t] = isfinite(mv) ? mv : 0.f;
    }
    __syncthreads();
    float acc = bp1[t];
    #pragma unroll
    for (int k = 0; k < 2 * Dd; k++) acc = fmaf(gv[k], Wp1[k * HID + t], acc);
    acc = fmaxf(acc, 0.f);
    acc = (acc - rm[t]) * rsqrtf(rv[t] + BN_EPS) * gamma[t] + beta[t];
    red[t] = acc * Wp2[t];
    __syncthreads();
    for (int s = 64; s > 0; s >>= 1) {
        if (t < s) red[t] += red[t + s];
        __syncthreads();
    }
    if (t == 0) out[g] = red[0] + bp2[0];
}

// ---------------- launch ----------------
extern "C" void kernel_launch(void* const* d_in, const int* in_sizes, int n_in,
                              void* d_out, int out_size) {
    const float* x     = (const float*)d_in[0];
    const int*   src   = (const int*)  d_in[1];
    const int*   dst   = (const int*)  d_in[2];
    const int*   gids  = (const int*)  d_in[3];
    const float* W1    = (const float*)d_in[4];
    const float* al1   = (const float*)d_in[5];
    const float* ar1   = (const float*)d_in[6];
    const float* b1    = (const float*)d_in[7];
    const float* resW1 = (const float*)d_in[8];
    const float* W2    = (const float*)d_in[9];
    const float* al2   = (const float*)d_in[10];
    const float* ar2   = (const float*)d_in[11];
    const float* b2    = (const float*)d_in[12];
    const float* Ww    = (const float*)d_in[13];
    const float* bw    = (const float*)d_in[14];
    const float* Wp1   = (const float*)d_in[15];
    const float* bp1   = (const float*)d_in[16];
    const float* gamma = (const float*)d_in[17];
    const float* beta  = (const float*)d_in[18];
    const float* rm    = (const float*)d_in[19];
    const float* rv    = (const float*)d_in[20];
    const float* Wp2   = (const float*)d_in[21];
    const float* bp2   = (const float*)d_in[22];
    float* out = (float*)d_out;

    int* pcnt;  cudaGetSymbolAddress((void**)&pcnt, g_cnt);
    float* pgs; cudaGetSymbolAddress((void**)&pgs, g_gsum);
    float* pgm; cudaGetSymbolAddress((void**)&pgm, g_gmax);
    float* ph1; cudaGetSymbolAddress((void**)&ph1, g_h1);

    static cudaStream_t s2 = nullptr;
    static cudaEvent_t e1 = nullptr, e2 = nullptr, e3 = nullptr, e4 = nullptr;
    if (!s2) {
        cudaStreamCreateWithFlags(&s2, cudaStreamNonBlocking);
        cudaEventCreateWithFlags(&e1, cudaEventDisableTiming);
        cudaEventCreateWithFlags(&e2, cudaEventDisableTiming);
        cudaEventCreateWithFlags(&e3, cudaEventDisableTiming);
        cudaEventCreateWithFlags(&e4, cudaEventDisableTiming);
    }

    const float NEG_INF = -INFINITY;
    const int NB = (Nn + 255) / 256;
    const int NA = SPLIT;              // chunk A node count
    const int NBC = Nn - SPLIT;        // chunk B node count

    cudaEventRecord(e1, 0);
    cudaStreamWaitEvent(s2, e1, 0);

    // ===== side stream: CSR build + readout-accumulator fills =====
    fill_int_kernel<<<NB, 256, 0, s2>>>(pcnt, Nn, 0);
    hist_kernel<<<(Ee + 255) / 256, 256, 0, s2>>>(dst);
    scan1_kernel<<<NB, 256, 0, s2>>>();
    scan2_kernel<<<1, 256, 0, s2>>>(NB);
    scan3_kernel<<<NB, 256, 0, s2>>>();
    scatter_kernel<<<(Ee + 255) / 256, 256, 0, s2>>>(src, dst);
    fill_kernel<<<(Gg * Dd + 255) / 256, 256, 0, s2>>>(pgs, Gg * Dd, 0.f);
    fill_kernel<<<(Gg * Dd + 255) / 256, 256, 0, s2>>>(pgm, Gg * Dd, NEG_INF);
    cudaEventRecord(e2, s2);

    // ===== main stream: layer 1 projection (overlaps CSR build) =====
    {
        dim3 grid(4, (Nn + 127) / 128);
        node1_tc_kernel<<<grid, 256>>>(x, W1, resW1, b1, al1, ar1);
    }
    cudaEventRecord(e3, 0);          // node1 done

    // main: wait CSR, then agg1 chunk A
    cudaStreamWaitEvent(0, e2, 0);
    agg1_kernel<<<NA / 8, 256>>>(0);
    // s2: after its own CSR work, wait node1, run agg1 chunk B (‖ gemm2 chunk A)
    cudaStreamWaitEvent(s2, e3, 0);
    agg1_kernel<<<(NBC + 7) / 8, 256, 0, s2>>>(SPLIT);
    cudaEventRecord(e4, s2);

    // main: gemm2 chunk A (rows [0, SPLIT)) — overlaps agg1 chunk B
    {
        dim3 grid(F / TBN, SPLIT / TBM);
        gemm2_tc_kernel<<<grid, 256>>>(ph1, W2, al2, ar2, 0);
    }
    // main: wait agg1 chunk B, then gemm2 chunk B
    cudaStreamWaitEvent(0, e4, 0);
    {
        dim3 grid(F / TBN, (NBC + TBM - 1) / TBM);
        gemm2_tc_kernel<<<grid, 256>>>(ph1, W2, al2, ar2, SPLIT);
    }

    // agg2 + MLP
    agg2_kernel<<<Nn / 8, 256>>>(b2, gids, Ww, bw);
    mlp_kernel<<<Gg, HID>>>(Wp1, bp1, gamma, beta, rm, rv, Wp2, bp2, out);
}

// round 12
// speedup vs baseline: 1.0723x; 1.0723x over previous
#include <cuda_runtime.h>
#include <cuda_bf16.h>
#include <math.h>
#include <cstdint>

#define Nn 50000
#define Ee 800000
#define INF 30
#define Hh 8
#define Dd 32
#define Gg 512
#define HID 128
#define ALPHA 0.2f
#define BN_EPS 1e-5f
#define F (Hh*Dd)   // 256
#define NSCAN 196   // ceil(Nn/256)

// ---------------- helpers ----------------
__device__ __forceinline__ unsigned f2tf32(float f) {
    unsigned u;
    asm("cvt.rna.tf32.f32 %0, %1;" : "=r"(u) : "f"(f));
    return u;
}

__device__ __forceinline__ void atomicMaxFloat(float* addr, float val) {
    int* ia = (int*)addr;
    int old = *ia;
    while (__int_as_float(old) < val) {
        int prev = atomicCAS(ia, old, __float_as_int(val));
        if (prev == old) break;
        old = prev;
    }
}

// ---------------- scratch (allocation-free: __device__ globals) ----------------
__device__ __nv_bfloat16 g_featb[Nn * F];  // projected features (bf16)
__device__ float g_base[Nn * F];     // layer1: b1 + x@resW1
__device__ float g_h1  [Nn * F];     // layer1 activation (fp32)
__device__ float g_el [Nn * Hh];
__device__ float g_er [Nn * Hh];
__device__ int   g_cnt [Nn];         // zero at rest (self-clearing)
__device__ int   g_rowptr[Nn + 1];
__device__ int   g_cursor[Nn];
__device__ int   g_csrc[Ee];
__device__ int   g_bsum[NSCAN];
__device__ float g_gsum[Gg * Dd];
__device__ float g_gmax[Gg * Dd];

__global__ void fill_kernel(float* p, int n, float val) {
    int i = blockIdx.x * blockDim.x + threadIdx.x;
    if (i < n) p[i] = val;
}

// ---------------- CSR build ----------------
__global__ void hist_kernel(const int* __restrict__ dst) {
    int e = blockIdx.x * blockDim.x + threadIdx.x;
    if (e < Ee) atomicAdd(&g_cnt[dst[e]], 1);
}

// part 1: block-local exclusive scan + block totals; clears g_cnt for next replay
__global__ void scan_p1_kernel() {
    __shared__ int sd[256];
    int t = threadIdx.x;
    int i = blockIdx.x * 256 + t;
    int v = (i < Nn) ? g_cnt[i] : 0;
    if (i < Nn) g_cnt[i] = 0;          // self-clear
    sd[t] = v;
    __syncthreads();
    #pragma unroll
    for (int off = 1; off < 256; off <<= 1) {
        int x = (t >= off) ? sd[t - off] : 0;
        __syncthreads();
        sd[t] += x;
        __syncthreads();
    }
    if (i < Nn) g_rowptr[i] = sd[t] - v;
    if (t == 255) g_bsum[blockIdx.x] = sd[255];
}

// part 2: each block redundantly reduces bsum[0..b) and applies offset
__global__ void scan_p2_kernel() {
    __shared__ int sd[256];
    int t = threadIdx.x;
    int b = blockIdx.x;
    sd[t] = (t < b && t < NSCAN) ? g_bsum[t] : 0;
    __syncthreads();
    #pragma unroll
    for (int s = 128; s > 0; s >>= 1) {
        if (t < s) sd[t] += sd[t + s];
        __syncthreads();
    }
    int off = sd[0];
    int i = b * 256 + t;
    if (i < Nn) {
        int r = g_rowptr[i] + off;
        g_rowptr[i] = r;
        g_cursor[i] = r;
    }
    if (b == 0 && t == 0) g_rowptr[Nn] = Ee;
}

__global__ void scatter_kernel(const int* __restrict__ src, const int* __restrict__ dst) {
    int e = blockIdx.x * blockDim.x + threadIdx.x;
    if (e >= Ee) return;
    int d = dst[e];
    int pos = atomicAdd(&g_cursor[d], 1);
    g_csrc[pos] = src[e];
}

// ================= layer-1 tensor-core projection =================
__global__ void node1_tc_kernel(const float* __restrict__ x,
                                const float* __restrict__ W1,
                                const float* __restrict__ resW1,
                                const float* __restrict__ b1,
                                const float* __restrict__ al1,
                                const float* __restrict__ ar1) {
    __shared__ float As[128][36];
    __shared__ float Bs[32][132];
    int tid = threadIdx.x;
    int lane = tid & 31, warp = tid >> 5;
    int g = lane >> 2, tig = lane & 3;
    int mw = (warp & 1) * 64;
    int nw = (warp >> 1) * 32;
    int rowBase = blockIdx.y * 128;
    int colBase = blockIdx.x * 128;     // 0,128 = feat; 256,384 = residual

    #pragma unroll
    for (int i = 0; i < 16; i++) {
        int id = tid + i * 256;
        int r = id >> 5, c = id & 31;
        int gr = rowBase + r;
        float v = (gr < Nn && c < INF) ? x[gr * INF + c] : 0.f;
        As[r][c] = __uint_as_float(f2tf32(v));
    }
    #pragma unroll
    for (int i = 0; i < 16; i++) {
        int id = tid + i * 256;
        int r = id >> 7, c = id & 127;
        int j = colBase + c;
        float v = 0.f;
        if (r < INF) v = (j < 256) ? W1[r * 256 + j] : resW1[r * 256 + (j - 256)];
        Bs[r][c] = __uint_as_float(f2tf32(v));
    }
    __syncthreads();

    float cf[4][4][4];
    #pragma unroll
    for (int mt = 0; mt < 4; mt++)
        #pragma unroll
        for (int nt = 0; nt < 4; nt++)
            #pragma unroll
            for (int q = 0; q < 4; q++) cf[mt][nt][q] = 0.f;

    #pragma unroll
    for (int k8 = 0; k8 < 32; k8 += 8) {
        unsigned a[4][4], b[4][2];
        #pragma unroll
        for (int mt = 0; mt < 4; mt++) {
            int r0 = mw + mt * 16;
            a[mt][0] = __float_as_uint(As[r0 + g][k8 + tig]);
            a[mt][1] = __float_as_uint(As[r0 + g + 8][k8 + tig]);
            a[mt][2] = __float_as_uint(As[r0 + g][k8 + tig + 4]);
            a[mt][3] = __float_as_uint(As[r0 + g + 8][k8 + tig + 4]);
        }
        #pragma unroll
        for (int nt = 0; nt < 4; nt++) {
            int cn = nw + nt * 8;
            b[nt][0] = __float_as_uint(Bs[k8 + tig][cn + g]);
            b[nt][1] = __float_as_uint(Bs[k8 + tig + 4][cn + g]);
        }
        #pragma unroll
        for (int mt = 0; mt < 4; mt++)
            #pragma unroll
            for (int nt = 0; nt < 4; nt++)
                asm volatile(
                    "mma.sync.aligned.m16n8k8.row.col.f32.tf32.tf32.f32 "
                    "{%0,%1,%2,%3},{%4,%5,%6,%7},{%8,%9},{%0,%1,%2,%3};"
                    : "+f"(cf[mt][nt][0]), "+f"(cf[mt][nt][1]),
                      "+f"(cf[mt][nt][2]), "+f"(cf[mt][nt][3])
                    : "r"(a[mt][0]), "r"(a[mt][1]), "r"(a[mt][2]), "r"(a[mt][3]),
                      "r"(b[nt][0]), "r"(b[nt][1]));
    }

    if (colBase < 256) {
        #pragma unroll
        for (int mt = 0; mt < 4; mt++) {
            int gr0 = rowBase + mw + mt * 16 + g;
            int gr1 = gr0 + 8;
            #pragma unroll
            for (int nt = 0; nt < 4; nt++) {
                int col = colBase + nw + nt * 8 + tig * 2;
                if (gr0 < Nn) {
                    __nv_bfloat162 p = __floats2bfloat162_rn(cf[mt][nt][0], cf[mt][nt][1]);
                    *(__nv_bfloat162*)&g_featb[gr0 * F + col] = p;
                }
                if (gr1 < Nn) {
                    __nv_bfloat162 p = __floats2bfloat162_rn(cf[mt][nt][2], cf[mt][nt][3]);
                    *(__nv_bfloat162*)&g_featb[gr1 * F + col] = p;
                }
            }
        }
        int hid = (colBase + nw) >> 5;
        float alv[4][2], arv[4][2];
        #pragma unroll
        for (int nt = 0; nt < 4; nt++) {
            int col = colBase + nw + nt * 8 + tig * 2;
            alv[nt][0] = al1[col]; alv[nt][1] = al1[col + 1];
            arv[nt][0] = ar1[col]; arv[nt][1] = ar1[col + 1];
        }
        #pragma unroll
        for (int mt = 0; mt < 4; mt++) {
            float el0 = 0.f, el1v = 0.f, er0 = 0.f, er1v = 0.f;
            #pragma unroll
            for (int nt = 0; nt < 4; nt++) {
                el0  += cf[mt][nt][0] * alv[nt][0] + cf[mt][nt][1] * alv[nt][1];
                el1v += cf[mt][nt][2] * alv[nt][0] + cf[mt][nt][3] * alv[nt][1];
                er0  += cf[mt][nt][0] * arv[nt][0] + cf[mt][nt][1] * arv[nt][1];
                er1v += cf[mt][nt][2] * arv[nt][0] + cf[mt][nt][3] * arv[nt][1];
            }
            el0  += __shfl_xor_sync(0xffffffffu, el0, 1);  el0  += __shfl_xor_sync(0xffffffffu, el0, 2);
            el1v += __shfl_xor_sync(0xffffffffu, el1v, 1); el1v += __shfl_xor_sync(0xffffffffu, el1v, 2);
            er0  += __shfl_xor_sync(0xffffffffu, er0, 1);  er0  += __shfl_xor_sync(0xffffffffu, er0, 2);
            er1v += __shfl_xor_sync(0xffffffffu, er1v, 1); er1v += __shfl_xor_sync(0xffffffffu, er1v, 2);
            if (tig == 0) {
                int gr0 = rowBase + mw + mt * 16 + g;
                int gr1 = gr0 + 8;
                if (gr0 < Nn) { g_el[gr0 * Hh + hid] = el0;  g_er[gr0 * Hh + hid] = er0; }
                if (gr1 < Nn) { g_el[gr1 * Hh + hid] = el1v; g_er[gr1 * Hh + hid] = er1v; }
            }
        }
    } else {
        #pragma unroll
        for (int mt = 0; mt < 4; mt++) {
            int gr0 = rowBase + mw + mt * 16 + g;
            int gr1 = gr0 + 8;
            #pragma unroll
            for (int nt = 0; nt < 4; nt++) {
                int j = colBase - 256 + nw + nt * 8 + tig * 2;
                float bj0 = b1[j], bj1 = b1[j + 1];
                if (gr0 < Nn) {
                    float2 v = make_float2(cf[mt][nt][0] + bj0, cf[mt][nt][1] + bj1);
                    *(float2*)&g_base[gr0 * F + j] = v;
                }
                if (gr1 < Nn) {
                    float2 v = make_float2(cf[mt][nt][2] + bj0, cf[mt][nt][3] + bj1);
                    *(float2*)&g_base[gr1 * F + j] = v;
                }
            }
        }
    }
}

// ---------------- layer 1: warp-per-node fused softmax + gather + ELU ----------------
__global__ void agg1_kernel() {
    int n = (blockIdx.x << 3) + (threadIdx.x >> 5);   // Nn % 8 == 0
    int lane = threadIdx.x & 31;
    int h = lane >> 2;
    float er_h = g_er[n * Hh + h];
    int start = g_rowptr[n];
    int deg = g_rowptr[n + 1] - start;

    float a0=0.f,a1=0.f,a2=0.f,a3=0.f,a4=0.f,a5=0.f,a6=0.f,a7=0.f;
    float ssum = 0.f;
    for (int c0 = 0; c0 < deg; c0 += 32) {
        int idx = c0 + lane;
        int s_l = (idx < deg) ? g_csrc[start + idx] : 0;
        int cnt = min(32, deg - c0);
        #pragma unroll 4
        for (int q = 0; q < cnt; q++) {
            int s = __shfl_sync(0xffffffffu, s_l, q);
            float v = g_el[s * Hh + h] + er_h;
            v = v > 0.f ? v : ALPHA * v;
            float ex = __expf(v);
            ssum += ex;
            uint4 u = *(const uint4*)&g_featb[s * F + lane * 8];
            float2 f0 = __bfloat1622float2(*(const __nv_bfloat162*)&u.x);
            float2 f1 = __bfloat1622float2(*(const __nv_bfloat162*)&u.y);
            float2 f2 = __bfloat1622float2(*(const __nv_bfloat162*)&u.z);
            float2 f3 = __bfloat1622float2(*(const __nv_bfloat162*)&u.w);
            a0 = fmaf(ex, f0.x, a0); a1 = fmaf(ex, f0.y, a1);
            a2 = fmaf(ex, f1.x, a2); a3 = fmaf(ex, f1.y, a3);
            a4 = fmaf(ex, f2.x, a4); a5 = fmaf(ex, f2.y, a5);
            a6 = fmaf(ex, f3.x, a6); a7 = fmaf(ex, f3.y, a7);
        }
    }
    float inv = 1.f / fmaxf(ssum, 1e-9f);

    float4 b0 = *(const float4*)&g_base[n * F + lane * 8];
    float4 b1v = *(const float4*)&g_base[n * F + lane * 8 + 4];
    float r0 = b0.x + a0 * inv, r1 = b0.y + a1 * inv;
    float r2 = b0.z + a2 * inv, r3 = b0.w + a3 * inv;
    float r4 = b1v.x + a4 * inv, r5 = b1v.y + a5 * inv;
    float r6 = b1v.z + a6 * inv, r7 = b1v.w + a7 * inv;
    r0 = r0 > 0.f ? r0 : (__expf(r0) - 1.f);
    r1 = r1 > 0.f ? r1 : (__expf(r1) - 1.f);
    r2 = r2 > 0.f ? r2 : (__expf(r2) - 1.f);
    r3 = r3 > 0.f ? r3 : (__expf(r3) - 1.f);
    r4 = r4 > 0.f ? r4 : (__expf(r4) - 1.f);
    r5 = r5 > 0.f ? r5 : (__expf(r5) - 1.f);
    r6 = r6 > 0.f ? r6 : (__expf(r6) - 1.f);
    r7 = r7 > 0.f ? r7 : (__expf(r7) - 1.f);
    *(float4*)&g_h1[n * F + lane * 8]     = make_float4(r0, r1, r2, r3);
    *(float4*)&g_h1[n * F + lane * 8 + 4] = make_float4(r4, r5, r6, r7);
}

// ---------------- layer 2: warp-per-node fused agg + head-mean + gated readout ----------------
__global__ void agg2_kernel(const float* __restrict__ b2,
                            const int* __restrict__ graph_ids,
                            const float* __restrict__ Ww,
                            const float* __restrict__ bw) {
    int n = (blockIdx.x << 3) + (threadIdx.x >> 5);
    int lane = threadIdx.x & 31;
    int h = lane >> 2;
    float er_h = g_er[n * Hh + h];
    int start = g_rowptr[n];
    int deg = g_rowptr[n + 1] - start;

    float a0=0.f,a1=0.f,a2=0.f,a3=0.f,a4=0.f,a5=0.f,a6=0.f,a7=0.f;
    float ssum = 0.f;
    for (int c0 = 0; c0 < deg; c0 += 32) {
        int idx = c0 + lane;
        int s_l = (idx < deg) ? g_csrc[start + idx] : 0;
        int cnt = min(32, deg - c0);
        #pragma unroll 4
        for (int q = 0; q < cnt; q++) {
            int s = __shfl_sync(0xffffffffu, s_l, q);
            float v = g_el[s * Hh + h] + er_h;
            v = v > 0.f ? v : ALPHA * v;
            float ex = __expf(v);
            ssum += ex;
            uint4 u = *(const uint4*)&g_featb[s * F + lane * 8];
            float2 f0 = __bfloat1622float2(*(const __nv_bfloat162*)&u.x);
            float2 f1 = __bfloat1622float2(*(const __nv_bfloat162*)&u.y);
            float2 f2 = __bfloat1622float2(*(const __nv_bfloat162*)&u.z);
            float2 f3 = __bfloat1622float2(*(const __nv_bfloat162*)&u.w);
            a0 = fmaf(ex, f0.x, a0); a1 = fmaf(ex, f0.y, a1);
            a2 = fmaf(ex, f1.x, a2); a3 = fmaf(ex, f1.y, a3);
            a4 = fmaf(ex, f2.x, a4); a5 = fmaf(ex, f2.y, a5);
            a6 = fmaf(ex, f3.x, a6); a7 = fmaf(ex, f3.y, a7);
        }
    }
    float inv = 1.f / fmaxf(ssum, 1e-9f);

    float4 h0v = *(const float4*)&g_h1[n * F + lane * 8];
    float4 h1v = *(const float4*)&g_h1[n * F + lane * 8 + 4];
    float4 bb0 = *(const float4*)&b2[lane * 8];
    float4 bb1 = *(const float4*)&b2[lane * 8 + 4];
    float r0 = h0v.x + bb0.x + a0 * inv, r1 = h0v.y + bb0.y + a1 * inv;
    float r2 = h0v.z + bb0.z + a2 * inv, r3 = h0v.w + bb0.w + a3 * inv;
    float r4 = h1v.x + bb1.x + a4 * inv, r5 = h1v.y + bb1.y + a5 * inv;
    float r6 = h1v.z + bb1.z + a6 * inv, r7 = h1v.w + bb1.w + a7 * inv;

    #pragma unroll
    for (int o = 4; o <= 16; o <<= 1) {
        r0 += __shfl_xor_sync(0xffffffffu, r0, o);
        r1 += __shfl_xor_sync(0xffffffffu, r1, o);
        r2 += __shfl_xor_sync(0xffffffffu, r2, o);
        r3 += __shfl_xor_sync(0xffffffffu, r3, o);
        r4 += __shfl_xor_sync(0xffffffffu, r4, o);
        r5 += __shfl_xor_sync(0xffffffffu, r5, o);
        r6 += __shfl_xor_sync(0xffffffffu, r6, o);
        r7 += __shfl_xor_sync(0xffffffffu, r7, o);
    }
    r0 *= 0.125f; r1 *= 0.125f; r2 *= 0.125f; r3 *= 0.125f;
    r4 *= 0.125f; r5 *= 0.125f; r6 *= 0.125f; r7 *= 0.125f;

    float partial = 0.f;
    if (lane < 4) {
        float4 w0 = *(const float4*)&Ww[lane * 8];
        float4 w1 = *(const float4*)&Ww[lane * 8 + 4];
        partial = r0 * w0.x + r1 * w0.y + r2 * w0.z + r3 * w0.w
                + r4 * w1.x + r5 * w1.y + r6 * w1.z + r7 * w1.w;
    }
    partial += __shfl_xor_sync(0xffffffffu, partial, 1);
    partial += __shfl_xor_sync(0xffffffffu, partial, 2);
    float w = 0.f;
    if (lane == 0) w = 1.f / (1.f + __expf(-(partial + bw[0])));
    w = __shfl_sync(0xffffffffu, w, 0);

    if (lane < 4) {
        int gid = graph_ids[n];
        float* gs = &g_gsum[gid * Dd + lane * 8];
        float* gm = &g_gmax[gid * Dd + lane * 8];
        atomicAdd(gs + 0, w * r0); atomicMaxFloat(gm + 0, r0);
        atomicAdd(gs + 1, w * r1); atomicMaxFloat(gm + 1, r1);
        atomicAdd(gs + 2, w * r2); atomicMaxFloat(gm + 2, r2);
        atomicAdd(gs + 3, w * r3); atomicMaxFloat(gm + 3, r3);
        atomicAdd(gs + 4, w * r4); atomicMaxFloat(gm + 4, r4);
        atomicAdd(gs + 5, w * r5); atomicMaxFloat(gm + 5, r5);
        atomicAdd(gs + 6, w * r6); atomicMaxFloat(gm + 6, r6);
        atomicAdd(gs + 7, w * r7); atomicMaxFloat(gm + 7, r7);
    }
}

// ======= layer-2 tf32 GEMM: featb=bf16(h1@W2) + fused el2/er2 epilogue =======
#define TBM 128
#define TBN 128
#define TBK 32
__global__ void gemm2_tc_kernel(const float* __restrict__ A, const float* __restrict__ B,
                                const float* __restrict__ al2, const float* __restrict__ ar2) {
    __shared__ float As[TBM][TBK + 4];
    __shared__ float Bs[TBK][TBN + 4];
    int tid = threadIdx.x;
    int lane = tid & 31, warp = tid >> 5;
    int g = lane >> 2, tig = lane & 3;
    int mw = (warp & 1) * 64;
    int nw = (warp >> 1) * 32;
    int rowBase = blockIdx.y * TBM;
    int colBase = blockIdx.x * TBN;

    float cf[4][4][4];
    #pragma unroll
    for (int mt = 0; mt < 4; mt++)
        #pragma unroll
        for (int nt = 0; nt < 4; nt++)
            #pragma unroll
            for (int q = 0; q < 4; q++) cf[mt][nt][q] = 0.f;

    for (int k0 = 0; k0 < F; k0 += TBK) {
        #pragma unroll
        for (int i = 0; i < 4; i++) {
            int id = tid + i * 256;
            int r = id >> 3, c4 = (id & 7) * 4;
            int gr = rowBase + r;
            float4 v = (gr < Nn) ? *(const float4*)&A[gr * F + k0 + c4]
                                 : make_float4(0.f, 0.f, 0.f, 0.f);
            uint4 u;
            u.x = f2tf32(v.x); u.y = f2tf32(v.y); u.z = f2tf32(v.z); u.w = f2tf32(v.w);
            *(uint4*)&As[r][c4] = u;
        }
        #pragma unroll
        for (int i = 0; i < 4; i++) {
            int id = tid + i * 256;
            int r = id >> 5, c4 = (id & 31) * 4;
            float4 v = *(const float4*)&B[(k0 + r) * F + colBase + c4];
            uint4 u;
            u.x = f2tf32(v.x); u.y = f2tf32(v.y); u.z = f2tf32(v.z); u.w = f2tf32(v.w);
            *(uint4*)&Bs[r][c4] = u;
        }
        __syncthreads();
        #pragma unroll
        for (int k8 = 0; k8 < TBK; k8 += 8) {
            unsigned a[4][4], b[4][2];
            #pragma unroll
            for (int mt = 0; mt < 4; mt++) {
                int r0 = mw + mt * 16;
                a[mt][0] = __float_as_uint(As[r0 + g][k8 + tig]);
                a[mt][1] = __float_as_uint(As[r0 + g + 8][k8 + tig]);
                a[mt][2] = __float_as_uint(As[r0 + g][k8 + tig + 4]);
                a[mt][3] = __float_as_uint(As[r0 + g + 8][k8 + tig + 4]);
            }
            #pragma unroll
            for (int nt = 0; nt < 4; nt++) {
                int cn = nw + nt * 8;
                b[nt][0] = __float_as_uint(Bs[k8 + tig][cn + g]);
                b[nt][1] = __float_as_uint(Bs[k8 + tig + 4][cn + g]);
            }
            #pragma unroll
            for (int mt = 0; mt < 4; mt++)
                #pragma unroll
                for (int nt = 0; nt < 4; nt++)
                    asm volatile(
                        "mma.sync.aligned.m16n8k8.row.col.f32.tf32.tf32.f32 "
                        "{%0,%1,%2,%3},{%4,%5,%6,%7},{%8,%9},{%0,%1,%2,%3};"
                        : "+f"(cf[mt][nt][0]), "+f"(cf[mt][nt][1]),
                          "+f"(cf[mt][nt][2]), "+f"(cf[mt][nt][3])
                        : "r"(a[mt][0]), "r"(a[mt][1]), "r"(a[mt][2]), "r"(a[mt][3]),
                          "r"(b[nt][0]), "r"(b[nt][1]));
        }
        __syncthreads();
    }

    #pragma unroll
    for (int mt = 0; mt < 4; mt++) {
        int gr0 = rowBase + mw + mt * 16 + g;
        int gr1 = gr0 + 8;
        #pragma unroll
        for (int nt = 0; nt < 4; nt++) {
            int col = colBase + nw + nt * 8 + tig * 2;
            if (gr0 < Nn) {
                __nv_bfloat162 p = __floats2bfloat162_rn(cf[mt][nt][0], cf[mt][nt][1]);
                *(__nv_bfloat162*)&g_featb[gr0 * F + col] = p;
            }
            if (gr1 < Nn) {
                __nv_bfloat162 p = __floats2bfloat162_rn(cf[mt][nt][2], cf[mt][nt][3]);
                *(__nv_bfloat162*)&g_featb[gr1 * F + col] = p;
            }
        }
    }
    int hid = (colBase + nw) >> 5;
    float alv[4][2], arv[4][2];
    #pragma unroll
    for (int nt = 0; nt < 4; nt++) {
        int col = colBase + nw + nt * 8 + tig * 2;
        alv[nt][0] = al2[col]; alv[nt][1] = al2[col + 1];
        arv[nt][0] = ar2[col]; arv[nt][1] = ar2[col + 1];
    }
    #pragma unroll
    for (int mt = 0; mt < 4; mt++) {
        float el0 = 0.f, el1v = 0.f, er0 = 0.f, er1v = 0.f;
        #pragma unroll
        for (int nt = 0; nt < 4; nt++) {
            el0  += cf[mt][nt][0] * alv[nt][0] + cf[mt][nt][1] * alv[nt][1];
            el1v += cf[mt][nt][2] * alv[nt][0] + cf[mt][nt][3] * alv[nt][1];
            er0  += cf[mt][nt][0] * arv[nt][0] + cf[mt][nt][1] * arv[nt][1];
            er1v += cf[mt][nt][2] * arv[nt][0] + cf[mt][nt][3] * arv[nt][1];
        }
        el0  += __shfl_xor_sync(0xffffffffu, el0, 1);  el0  += __shfl_xor_sync(0xffffffffu, el0, 2);
        el1v += __shfl_xor_sync(0xffffffffu, el1v, 1); el1v += __shfl_xor_sync(0xffffffffu, el1v, 2);
        er0  += __shfl_xor_sync(0xffffffffu, er0, 1);  er0  += __shfl_xor_sync(0xffffffffu, er0, 2);
        er1v += __shfl_xor_sync(0xffffffffu, er1v, 1); er1v += __shfl_xor_sync(0xffffffffu, er1v, 2);
        if (tig == 0) {
            int gr0 = rowBase + mw + mt * 16 + g;
            int gr1 = gr0 + 8;
            if (gr0 < Nn) { g_el[gr0 * Hh + hid] = el0;  g_er[gr0 * Hh + hid] = er0; }
            if (gr1 < Nn) { g_el[gr1 * Hh + hid] = el1v; g_er[gr1 * Hh + hid] = er1v; }
        }
    }
}

// ---------------- MLP head ----------------
__global__ void mlp_kernel(const float* __restrict__ Wp1, const float* __restrict__ bp1,
                           const float* __restrict__ gamma, const float* __restrict__ beta,
                           const float* __restrict__ rm, const float* __restrict__ rv,
                           const float* __restrict__ Wp2, const float* __restrict__ bp2,
                           float* __restrict__ out) {
    int g = blockIdx.x;
    int t = threadIdx.x;      // 0..127
    __shared__ float gv[2 * Dd];
    __shared__ float red[HID];
    if (t < Dd) gv[t] = g_gsum[g * Dd + t];
    else if (t < 2 * Dd) {
        float mv = g_gmax[g * Dd + (t - Dd)];
        gv[t] = isfinite(mv) ? mv : 0.f;
    }
    __syncthreads();
    float acc = bp1[t];
    #pragma unroll
    for (int k = 0; k < 2 * Dd; k++) acc = fmaf(gv[k], Wp1[k * HID + t], acc);
    acc = fmaxf(acc, 0.f);
    acc = (acc - rm[t]) * rsqrtf(rv[t] + BN_EPS) * gamma[t] + beta[t];
    red[t] = acc * Wp2[t];
    __syncthreads();
    for (int s = 64; s > 0; s >>= 1) {
        if (t < s) red[t] += red[t + s];
        __syncthreads();
    }
    if (t == 0) out[g] = red[0] + bp2[0];
}

// ---------------- launch ----------------
extern "C" void kernel_launch(void* const* d_in, const int* in_sizes, int n_in,
                              void* d_out, int out_size) {
    const float* x     = (const float*)d_in[0];
    const int*   src   = (const int*)  d_in[1];
    const int*   dst   = (const int*)  d_in[2];
    const int*   gids  = (const int*)  d_in[3];
    const float* W1    = (const float*)d_in[4];
    const float* al1   = (const float*)d_in[5];
    const float* ar1   = (const float*)d_in[6];
    const float* b1    = (const float*)d_in[7];
    const float* resW1 = (const float*)d_in[8];
    const float* W2    = (const float*)d_in[9];
    const float* al2   = (const float*)d_in[10];
    const float* ar2   = (const float*)d_in[11];
    const float* b2    = (const float*)d_in[12];
    const float* Ww    = (const float*)d_in[13];
    const float* bw    = (const float*)d_in[14];
    const float* Wp1   = (const float*)d_in[15];
    const float* bp1   = (const float*)d_in[16];
    const float* gamma = (const float*)d_in[17];
    const float* beta  = (const float*)d_in[18];
    const float* rm    = (const float*)d_in[19];
    const float* rv    = (const float*)d_in[20];
    const float* Wp2   = (const float*)d_in[21];
    const float* bp2   = (const float*)d_in[22];
    float* out = (float*)d_out;

    float* pgs; cudaGetSymbolAddress((void**)&pgs, g_gsum);
    float* pgm; cudaGetSymbolAddress((void**)&pgm, g_gmax);
    float* ph1; cudaGetSymbolAddress((void**)&ph1, g_h1);

    static cudaStream_t s2 = nullptr;
    static cudaEvent_t e1 = nullptr, e2 = nullptr;
    if (!s2) {
        cudaStreamCreateWithFlags(&s2, cudaStreamNonBlocking);
        cudaEventCreateWithFlags(&e1, cudaEventDisableTiming);
        cudaEventCreateWithFlags(&e2, cudaEventDisableTiming);
    }

    const float NEG_INF = -INFINITY;

    cudaEventRecord(e1, 0);
    cudaStreamWaitEvent(s2, e1, 0);

    // ===== side stream: CSR build (self-clearing cnt; 2-kernel scan) + fills =====
    hist_kernel<<<(Ee + 255) / 256, 256, 0, s2>>>(dst);
    scan_p1_kernel<<<NSCAN, 256, 0, s2>>>();
    scan_p2_kernel<<<NSCAN, 256, 0, s2>>>();
    scatter_kernel<<<(Ee + 255) / 256, 256, 0, s2>>>(src, dst);
    fill_kernel<<<(Gg * Dd + 255) / 256, 256, 0, s2>>>(pgs, Gg * Dd, 0.f);
    fill_kernel<<<(Gg * Dd + 255) / 256, 256, 0, s2>>>(pgm, Gg * Dd, NEG_INF);
    cudaEventRecord(e2, s2);

    // ===== main stream: layer 1 tensor-core projection (overlaps CSR build) =====
    {
        dim3 grid(4, (Nn + 127) / 128);
        node1_tc_kernel<<<grid, 256>>>(x, W1, resW1, b1, al1, ar1);
    }

    cudaStreamWaitEvent(0, e2, 0);
    agg1_kernel<<<Nn / 8, 256>>>();

    // ===== layer 2 =====
    {
        dim3 grid(F / TBN, (Nn + TBM - 1) / TBM);
        gemm2_tc_kernel<<<grid, 256>>>(ph1, W2, al2, ar2);
    }
    agg2_kernel<<<Nn / 8, 256>>>(b2, gids, Ww, bw);

    // ===== MLP =====
    mlp_kernel<<<Gg, HID>>>(Wp1, bp1, gamma, beta, rm, rv, Wp2, bp2, out);
}

// round 13
// speedup vs baseline: 1.1153x; 1.0401x over previous
#include <cuda_runtime.h>
#include <cuda_bf16.h>
#include <math.h>
#include <cstdint>

#define Nn 50000
#define Ee 800000
#define INF 30
#define Hh 8
#define Dd 32
#define Gg 512
#define HID 128
#define ALPHA 0.2f
#define BN_EPS 1e-5f
#define F (Hh*Dd)   // 256
#define NSCAN 196   // ceil(Nn/256)

// ---------------- helpers ----------------
__device__ __forceinline__ unsigned f2tf32(float f) {
    unsigned u;
    asm("cvt.rna.tf32.f32 %0, %1;" : "=r"(u) : "f"(f));
    return u;
}

__device__ __forceinline__ void atomicMaxFloat(float* addr, float val) {
    int* ia = (int*)addr;
    int old = *ia;
    while (__int_as_float(old) < val) {
        int prev = atomicCAS(ia, old, __float_as_int(val));
        if (prev == old) break;
        old = prev;
    }
}

__device__ __forceinline__ void cp_async16(unsigned sa, const void* gp, int nbytes) {
    asm volatile("cp.async.cg.shared.global [%0], [%1], 16, %2;"
                 :: "r"(sa), "l"(gp), "r"(nbytes));
}
__device__ __forceinline__ void cp_commit() {
    asm volatile("cp.async.commit_group;");
}
template<int N>
__device__ __forceinline__ void cp_wait() {
    asm volatile("cp.async.wait_group %0;" :: "n"(N));
}

// ---------------- scratch (allocation-free: __device__ globals) ----------------
__device__ __nv_bfloat16 g_featb[Nn * F];  // projected features (bf16)
__device__ float g_base[Nn * F];     // layer1: b1 + x@resW1
__device__ float g_h1  [Nn * F];     // layer1 activation (fp32)
__device__ float g_el [Nn * Hh];
__device__ float g_er [Nn * Hh];
__device__ int   g_cnt [Nn];         // zero at rest (self-clearing)
__device__ int   g_rowptr[Nn + 1];
__device__ int   g_cursor[Nn];
__device__ int   g_csrc[Ee];
__device__ int   g_bsum[NSCAN];
__device__ float g_gsum[Gg * Dd];
__device__ float g_gmax[Gg * Dd];

// ---------------- CSR build ----------------
__global__ void hist_kernel(const int* __restrict__ dst) {
    int e = blockIdx.x * blockDim.x + threadIdx.x;
    if (e < Ee) atomicAdd(&g_cnt[dst[e]], 1);
}

// part 1: block-local exclusive scan + block totals; clears g_cnt for next replay
__global__ void scan_p1_kernel() {
    __shared__ int sd[256];
    int t = threadIdx.x;
    int i = blockIdx.x * 256 + t;
    int v = (i < Nn) ? g_cnt[i] : 0;
    if (i < Nn) g_cnt[i] = 0;          // self-clear
    sd[t] = v;
    __syncthreads();
    #pragma unroll
    for (int off = 1; off < 256; off <<= 1) {
        int x = (t >= off) ? sd[t - off] : 0;
        __syncthreads();
        sd[t] += x;
        __syncthreads();
    }
    if (i < Nn) g_rowptr[i] = sd[t] - v;
    if (t == 255) g_bsum[blockIdx.x] = sd[255];
}

// part 2: each block redundantly reduces bsum[0..b), applies offset, and
// initializes the readout accumulators (folded fills).
__global__ void scan_p2_kernel() {
    __shared__ int sd[256];
    int t = threadIdx.x;
    int b = blockIdx.x;
    sd[t] = (t < b && t < NSCAN) ? g_bsum[t] : 0;
    __syncthreads();
    #pragma unroll
    for (int s = 128; s > 0; s >>= 1) {
        if (t < s) sd[t] += sd[t + s];
        __syncthreads();
    }
    int off = sd[0];
    int i = b * 256 + t;
    if (i < Nn) {
        int r = g_rowptr[i] + off;
        g_rowptr[i] = r;
        g_cursor[i] = r;
    }
    if (i < Gg * Dd) {
        g_gsum[i] = 0.f;
        g_gmax[i] = -INFINITY;
    }
    if (b == 0 && t == 0) g_rowptr[Nn] = Ee;
}

__global__ void scatter_kernel(const int* __restrict__ src, const int* __restrict__ dst) {
    int e = blockIdx.x * blockDim.x + threadIdx.x;
    if (e >= Ee) return;
    int d = dst[e];
    int pos = atomicAdd(&g_cursor[d], 1);
    g_csrc[pos] = src[e];
}

// ================= layer-1 tensor-core projection =================
__global__ void node1_tc_kernel(const float* __restrict__ x,
                                const float* __restrict__ W1,
                                const float* __restrict__ resW1,
                                const float* __restrict__ b1,
                                const float* __restrict__ al1,
                                const float* __restrict__ ar1) {
    __shared__ float As[128][36];
    __shared__ float Bs[32][132];
    int tid = threadIdx.x;
    int lane = tid & 31, warp = tid >> 5;
    int g = lane >> 2, tig = lane & 3;
    int mw = (warp & 1) * 64;
    int nw = (warp >> 1) * 32;
    int rowBase = blockIdx.y * 128;
    int colBase = blockIdx.x * 128;     // 0,128 = feat; 256,384 = residual

    #pragma unroll
    for (int i = 0; i < 16; i++) {
        int id = tid + i * 256;
        int r = id >> 5, c = id & 31;
        int gr = rowBase + r;
        float v = (gr < Nn && c < INF) ? x[gr * INF + c] : 0.f;
        As[r][c] = __uint_as_float(f2tf32(v));
    }
    #pragma unroll
    for (int i = 0; i < 16; i++) {
        int id = tid + i * 256;
        int r = id >> 7, c = id & 127;
        int j = colBase + c;
        float v = 0.f;
        if (r < INF) v = (j < 256) ? W1[r * 256 + j] : resW1[r * 256 + (j - 256)];
        Bs[r][c] = __uint_as_float(f2tf32(v));
    }
    __syncthreads();

    float cf[4][4][4];
    #pragma unroll
    for (int mt = 0; mt < 4; mt++)
        #pragma unroll
        for (int nt = 0; nt < 4; nt++)
            #pragma unroll
            for (int q = 0; q < 4; q++) cf[mt][nt][q] = 0.f;

    #pragma unroll
    for (int k8 = 0; k8 < 32; k8 += 8) {
        unsigned a[4][4], b[4][2];
        #pragma unroll
        for (int mt = 0; mt < 4; mt++) {
            int r0 = mw + mt * 16;
            a[mt][0] = __float_as_uint(As[r0 + g][k8 + tig]);
            a[mt][1] = __float_as_uint(As[r0 + g + 8][k8 + tig]);
            a[mt][2] = __float_as_uint(As[r0 + g][k8 + tig + 4]);
            a[mt][3] = __float_as_uint(As[r0 + g + 8][k8 + tig + 4]);
        }
        #pragma unroll
        for (int nt = 0; nt < 4; nt++) {
            int cn = nw + nt * 8;
            b[nt][0] = __float_as_uint(Bs[k8 + tig][cn + g]);
            b[nt][1] = __float_as_uint(Bs[k8 + tig + 4][cn + g]);
        }
        #pragma unroll
        for (int mt = 0; mt < 4; mt++)
            #pragma unroll
            for (int nt = 0; nt < 4; nt++)
                asm volatile(
                    "mma.sync.aligned.m16n8k8.row.col.f32.tf32.tf32.f32 "
                    "{%0,%1,%2,%3},{%4,%5,%6,%7},{%8,%9},{%0,%1,%2,%3};"
                    : "+f"(cf[mt][nt][0]), "+f"(cf[mt][nt][1]),
                      "+f"(cf[mt][nt][2]), "+f"(cf[mt][nt][3])
                    : "r"(a[mt][0]), "r"(a[mt][1]), "r"(a[mt][2]), "r"(a[mt][3]),
                      "r"(b[nt][0]), "r"(b[nt][1]));
    }

    if (colBase < 256) {
        #pragma unroll
        for (int mt = 0; mt < 4; mt++) {
            int gr0 = rowBase + mw + mt * 16 + g;
            int gr1 = gr0 + 8;
            #pragma unroll
            for (int nt = 0; nt < 4; nt++) {
                int col = colBase + nw + nt * 8 + tig * 2;
                if (gr0 < Nn) {
                    __nv_bfloat162 p = __floats2bfloat162_rn(cf[mt][nt][0], cf[mt][nt][1]);
                    *(__nv_bfloat162*)&g_featb[gr0 * F + col] = p;
                }
                if (gr1 < Nn) {
                    __nv_bfloat162 p = __floats2bfloat162_rn(cf[mt][nt][2], cf[mt][nt][3]);
                    *(__nv_bfloat162*)&g_featb[gr1 * F + col] = p;
                }
            }
        }
        int hid = (colBase + nw) >> 5;
        float alv[4][2], arv[4][2];
        #pragma unroll
        for (int nt = 0; nt < 4; nt++) {
            int col = colBase + nw + nt * 8 + tig * 2;
            alv[nt][0] = al1[col]; alv[nt][1] = al1[col + 1];
            arv[nt][0] = ar1[col]; arv[nt][1] = ar1[col + 1];
        }
        #pragma unroll
        for (int mt = 0; mt < 4; mt++) {
            float el0 = 0.f, el1v = 0.f, er0 = 0.f, er1v = 0.f;
            #pragma unroll
            for (int nt = 0; nt < 4; nt++) {
                el0  += cf[mt][nt][0] * alv[nt][0] + cf[mt][nt][1] * alv[nt][1];
                el1v += cf[mt][nt][2] * alv[nt][0] + cf[mt][nt][3] * alv[nt][1];
                er0  += cf[mt][nt][0] * arv[nt][0] + cf[mt][nt][1] * arv[nt][1];
                er1v += cf[mt][nt][2] * arv[nt][0] + cf[mt][nt][3] * arv[nt][1];
            }
            el0  += __shfl_xor_sync(0xffffffffu, el0, 1);  el0  += __shfl_xor_sync(0xffffffffu, el0, 2);
            el1v += __shfl_xor_sync(0xffffffffu, el1v, 1); el1v += __shfl_xor_sync(0xffffffffu, el1v, 2);
            er0  += __shfl_xor_sync(0xffffffffu, er0, 1);  er0  += __shfl_xor_sync(0xffffffffu, er0, 2);
            er1v += __shfl_xor_sync(0xffffffffu, er1v, 1); er1v += __shfl_xor_sync(0xffffffffu, er1v, 2);
            if (tig == 0) {
                int gr0 = rowBase + mw + mt * 16 + g;
                int gr1 = gr0 + 8;
                if (gr0 < Nn) { g_el[gr0 * Hh + hid] = el0;  g_er[gr0 * Hh + hid] = er0; }
                if (gr1 < Nn) { g_el[gr1 * Hh + hid] = el1v; g_er[gr1 * Hh + hid] = er1v; }
            }
        }
    } else {
        #pragma unroll
        for (int mt = 0; mt < 4; mt++) {
            int gr0 = rowBase + mw + mt * 16 + g;
            int gr1 = gr0 + 8;
            #pragma unroll
            for (int nt = 0; nt < 4; nt++) {
                int j = colBase - 256 + nw + nt * 8 + tig * 2;
                float bj0 = b1[j], bj1 = b1[j + 1];
                if (gr0 < Nn) {
                    float2 v = make_float2(cf[mt][nt][0] + bj0, cf[mt][nt][1] + bj1);
                    *(float2*)&g_base[gr0 * F + j] = v;
                }
                if (gr1 < Nn) {
                    float2 v = make_float2(cf[mt][nt][2] + bj0, cf[mt][nt][3] + bj1);
                    *(float2*)&g_base[gr1 * F + j] = v;
                }
            }
        }
    }
}

// ---------------- layer 1: warp-per-node fused softmax + gather + ELU ----------------
__global__ void agg1_kernel() {
    int n = (blockIdx.x << 3) + (threadIdx.x >> 5);   // Nn % 8 == 0
    int lane = threadIdx.x & 31;
    int h = lane >> 2;
    float er_h = g_er[n * Hh + h];
    int start = g_rowptr[n];
    int deg = g_rowptr[n + 1] - start;

    float a0=0.f,a1=0.f,a2=0.f,a3=0.f,a4=0.f,a5=0.f,a6=0.f,a7=0.f;
    float ssum = 0.f;
    for (int c0 = 0; c0 < deg; c0 += 32) {
        int idx = c0 + lane;
        int s_l = (idx < deg) ? g_csrc[start + idx] : 0;
        int cnt = min(32, deg - c0);
        #pragma unroll 4
        for (int q = 0; q < cnt; q++) {
            int s = __shfl_sync(0xffffffffu, s_l, q);
            float v = g_el[s * Hh + h] + er_h;
            v = v > 0.f ? v : ALPHA * v;
            float ex = __expf(v);
            ssum += ex;
            uint4 u = *(const uint4*)&g_featb[s * F + lane * 8];
            float2 f0 = __bfloat1622float2(*(const __nv_bfloat162*)&u.x);
            float2 f1 = __bfloat1622float2(*(const __nv_bfloat162*)&u.y);
            float2 f2 = __bfloat1622float2(*(const __nv_bfloat162*)&u.z);
            float2 f3 = __bfloat1622float2(*(const __nv_bfloat162*)&u.w);
            a0 = fmaf(ex, f0.x, a0); a1 = fmaf(ex, f0.y, a1);
            a2 = fmaf(ex, f1.x, a2); a3 = fmaf(ex, f1.y, a3);
            a4 = fmaf(ex, f2.x, a4); a5 = fmaf(ex, f2.y, a5);
            a6 = fmaf(ex, f3.x, a6); a7 = fmaf(ex, f3.y, a7);
        }
    }
    float inv = 1.f / fmaxf(ssum, 1e-9f);

    float4 b0 = *(const float4*)&g_base[n * F + lane * 8];
    float4 b1v = *(const float4*)&g_base[n * F + lane * 8 + 4];
    float r0 = b0.x + a0 * inv, r1 = b0.y + a1 * inv;
    float r2 = b0.z + a2 * inv, r3 = b0.w + a3 * inv;
    float r4 = b1v.x + a4 * inv, r5 = b1v.y + a5 * inv;
    float r6 = b1v.z + a6 * inv, r7 = b1v.w + a7 * inv;
    r0 = r0 > 0.f ? r0 : (__expf(r0) - 1.f);
    r1 = r1 > 0.f ? r1 : (__expf(r1) - 1.f);
    r2 = r2 > 0.f ? r2 : (__expf(r2) - 1.f);
    r3 = r3 > 0.f ? r3 : (__expf(r3) - 1.f);
    r4 = r4 > 0.f ? r4 : (__expf(r4) - 1.f);
    r5 = r5 > 0.f ? r5 : (__expf(r5) - 1.f);
    r6 = r6 > 0.f ? r6 : (__expf(r6) - 1.f);
    r7 = r7 > 0.f ? r7 : (__expf(r7) - 1.f);
    *(float4*)&g_h1[n * F + lane * 8]     = make_float4(r0, r1, r2, r3);
    *(float4*)&g_h1[n * F + lane * 8 + 4] = make_float4(r4, r5, r6, r7);
}

// ---------------- layer 2: warp-per-node fused agg + head-mean + gated readout ----------------
__global__ void agg2_kernel(const float* __restrict__ b2,
                            const int* __restrict__ graph_ids,
                            const float* __restrict__ Ww,
                            const float* __restrict__ bw) {
    int n = (blockIdx.x << 3) + (threadIdx.x >> 5);
    int lane = threadIdx.x & 31;
    int h = lane >> 2;
    float er_h = g_er[n * Hh + h];
    int start = g_rowptr[n];
    int deg = g_rowptr[n + 1] - start;

    float a0=0.f,a1=0.f,a2=0.f,a3=0.f,a4=0.f,a5=0.f,a6=0.f,a7=0.f;
    float ssum = 0.f;
    for (int c0 = 0; c0 < deg; c0 += 32) {
        int idx = c0 + lane;
        int s_l = (idx < deg) ? g_csrc[start + idx] : 0;
        int cnt = min(32, deg - c0);
        #pragma unroll 4
        for (int q = 0; q < cnt; q++) {
            int s = __shfl_sync(0xffffffffu, s_l, q);
            float v = g_el[s * Hh + h] + er_h;
            v = v > 0.f ? v : ALPHA * v;
            float ex = __expf(v);
            ssum += ex;
            uint4 u = *(const uint4*)&g_featb[s * F + lane * 8];
            float2 f0 = __bfloat1622float2(*(const __nv_bfloat162*)&u.x);
            float2 f1 = __bfloat1622float2(*(const __nv_bfloat162*)&u.y);
            float2 f2 = __bfloat1622float2(*(const __nv_bfloat162*)&u.z);
            float2 f3 = __bfloat1622float2(*(const __nv_bfloat162*)&u.w);
            a0 = fmaf(ex, f0.x, a0); a1 = fmaf(ex, f0.y, a1);
            a2 = fmaf(ex, f1.x, a2); a3 = fmaf(ex, f1.y, a3);
            a4 = fmaf(ex, f2.x, a4); a5 = fmaf(ex, f2.y, a5);
            a6 = fmaf(ex, f3.x, a6); a7 = fmaf(ex, f3.y, a7);
        }
    }
    float inv = 1.f / fmaxf(ssum, 1e-9f);

    float4 h0v = *(const float4*)&g_h1[n * F + lane * 8];
    float4 h1v = *(const float4*)&g_h1[n * F + lane * 8 + 4];
    float4 bb0 = *(const float4*)&b2[lane * 8];
    float4 bb1 = *(const float4*)&b2[lane * 8 + 4];
    float r0 = h0v.x + bb0.x + a0 * inv, r1 = h0v.y + bb0.y + a1 * inv;
    float r2 = h0v.z + bb0.z + a2 * inv, r3 = h0v.w + bb0.w + a3 * inv;
    float r4 = h1v.x + bb1.x + a4 * inv, r5 = h1v.y + bb1.y + a5 * inv;
    float r6 = h1v.z + bb1.z + a6 * inv, r7 = h1v.w + bb1.w + a7 * inv;

    #pragma unroll
    for (int o = 4; o <= 16; o <<= 1) {
        r0 += __shfl_xor_sync(0xffffffffu, r0, o);
        r1 += __shfl_xor_sync(0xffffffffu, r1, o);
        r2 += __shfl_xor_sync(0xffffffffu, r2, o);
        r3 += __shfl_xor_sync(0xffffffffu, r3, o);
        r4 += __shfl_xor_sync(0xffffffffu, r4, o);
        r5 += __shfl_xor_sync(0xffffffffu, r5, o);
        r6 += __shfl_xor_sync(0xffffffffu, r6, o);
        r7 += __shfl_xor_sync(0xffffffffu, r7, o);
    }
    r0 *= 0.125f; r1 *= 0.125f; r2 *= 0.125f; r3 *= 0.125f;
    r4 *= 0.125f; r5 *= 0.125f; r6 *= 0.125f; r7 *= 0.125f;

    float partial = 0.f;
    if (lane < 4) {
        float4 w0 = *(const float4*)&Ww[lane * 8];
        float4 w1 = *(const float4*)&Ww[lane * 8 + 4];
        partial = r0 * w0.x + r1 * w0.y + r2 * w0.z + r3 * w0.w
                + r4 * w1.x + r5 * w1.y + r6 * w1.z + r7 * w1.w;
    }
    partial += __shfl_xor_sync(0xffffffffu, partial, 1);
    partial += __shfl_xor_sync(0xffffffffu, partial, 2);
    float w = 0.f;
    if (lane == 0) w = 1.f / (1.f + __expf(-(partial + bw[0])));
    w = __shfl_sync(0xffffffffu, w, 0);

    if (lane < 4) {
        int gid = graph_ids[n];
        float* gs = &g_gsum[gid * Dd + lane * 8];
        float* gm = &g_gmax[gid * Dd + lane * 8];
        atomicAdd(gs + 0, w * r0); atomicMaxFloat(gm + 0, r0);
        atomicAdd(gs + 1, w * r1); atomicMaxFloat(gm + 1, r1);
        atomicAdd(gs + 2, w * r2); atomicMaxFloat(gm + 2, r2);
        atomicAdd(gs + 3, w * r3); atomicMaxFloat(gm + 3, r3);
        atomicAdd(gs + 4, w * r4); atomicMaxFloat(gm + 4, r4);
        atomicAdd(gs + 5, w * r5); atomicMaxFloat(gm + 5, r5);
        atomicAdd(gs + 6, w * r6); atomicMaxFloat(gm + 6, r6);
        atomicAdd(gs + 7, w * r7); atomicMaxFloat(gm + 7, r7);
    }
}

// ======= layer-2 tf32 GEMM, 2-stage cp.async pipeline =======
// featb = bf16(h1 @ W2) + fused el2/er2 epilogue.
#define TBM 128
#define TBN 128
#define TBK 32
#define AS_STRIDE (TBK + 4)         // 36 floats per A row (16B-aligned: 144B)
#define BS_STRIDE (TBN + 4)         // 132 floats per B row (16B-aligned: 528B)
#define AS_STAGE (TBM * AS_STRIDE)  // 4608 floats
#define BS_STAGE (TBK * BS_STRIDE)  // 4224 floats
#define SMEM_GEMM ((2 * (AS_STAGE + BS_STAGE)) * 4)   // 70656 B

__global__ void __launch_bounds__(256, 2)
gemm2_tc_kernel(const float* __restrict__ A, const float* __restrict__ B,
                const float* __restrict__ al2, const float* __restrict__ ar2) {
    extern __shared__ float smemf[];
    float* Asm = smemf;                     // [2][TBM][AS_STRIDE]
    float* Bsm = smemf + 2 * AS_STAGE;      // [2][TBK][BS_STRIDE]

    int tid = threadIdx.x;
    int lane = tid & 31, warp = tid >> 5;
    int g = lane >> 2, tig = lane & 3;
    int mw = (warp & 1) * 64;
    int nw = (warp >> 1) * 32;
    int rowBase = blockIdx.y * TBM;
    int colBase = blockIdx.x * TBN;

    // cp.async tile loaders: A = 128 rows x 32 floats (8x16B chunks/row), 4 chunks/thread
    //                        B = 32 rows x 128 floats (32x16B chunks/row), 4 chunks/thread
    auto load_tiles = [&](int st, int k0) {
        #pragma unroll
        for (int i = 0; i < 4; i++) {
            int id = tid + i * 256;
            int r = id >> 3, cq = (id & 7) * 4;
            int gr = rowBase + r;
            unsigned sa = (unsigned)__cvta_generic_to_shared(
                &Asm[st * AS_STAGE + r * AS_STRIDE + cq]);
            const float* gp = &A[(long)gr * F + k0 + cq];
            cp_async16(sa, gp, (gr < Nn) ? 16 : 0);
        }
        #pragma unroll
        for (int i = 0; i < 4; i++) {
            int id = tid + i * 256;
            int r = id >> 5, cq = (id & 31) * 4;
            unsigned sa = (unsigned)__cvta_generic_to_shared(
                &Bsm[st * BS_STAGE + r * BS_STRIDE + cq]);
            const float* gp = &B[(long)(k0 + r) * F + colBase + cq];
            cp_async16(sa, gp, 16);
        }
        cp_commit();
    };

    float cf[4][4][4];
    #pragma unroll
    for (int mt = 0; mt < 4; mt++)
        #pragma unroll
        for (int nt = 0; nt < 4; nt++)
            #pragma unroll
            for (int q = 0; q < 4; q++) cf[mt][nt][q] = 0.f;

    int st = 0;
    load_tiles(0, 0);

    #pragma unroll
    for (int ki = 0; ki < F / TBK; ki++) {
        if (ki + 1 < F / TBK) {
            load_tiles(st ^ 1, (ki + 1) * TBK);
            cp_wait<1>();
        } else {
            cp_wait<0>();
        }
        __syncthreads();

        const float* As = &Asm[st * AS_STAGE];
        const float* Bsp = &Bsm[st * BS_STAGE];
        #pragma unroll
        for (int k8 = 0; k8 < TBK; k8 += 8) {
            unsigned a[4][4], b[4][2];
            #pragma unroll
            for (int mt = 0; mt < 4; mt++) {
                int r0 = mw + mt * 16;
                a[mt][0] = f2tf32(As[(r0 + g) * AS_STRIDE + k8 + tig]);
                a[mt][1] = f2tf32(As[(r0 + g + 8) * AS_STRIDE + k8 + tig]);
                a[mt][2] = f2tf32(As[(r0 + g) * AS_STRIDE + k8 + tig + 4]);
                a[mt][3] = f2tf32(As[(r0 + g + 8) * AS_STRIDE + k8 + tig + 4]);
            }
            #pragma unroll
            for (int nt = 0; nt < 4; nt++) {
                int cn = nw + nt * 8;
                b[nt][0] = f2tf32(Bsp[(k8 + tig) * BS_STRIDE + cn + g]);
                b[nt][1] = f2tf32(Bsp[(k8 + tig + 4) * BS_STRIDE + cn + g]);
            }
            #pragma unroll
            for (int mt = 0; mt < 4; mt++)
                #pragma unroll
                for (int nt = 0; nt < 4; nt++)
                    asm volatile(
                        "mma.sync.aligned.m16n8k8.row.col.f32.tf32.tf32.f32 "
                        "{%0,%1,%2,%3},{%4,%5,%6,%7},{%8,%9},{%0,%1,%2,%3};"
                        : "+f"(cf[mt][nt][0]), "+f"(cf[mt][nt][1]),
                          "+f"(cf[mt][nt][2]), "+f"(cf[mt][nt][3])
                        : "r"(a[mt][0]), "r"(a[mt][1]), "r"(a[mt][2]), "r"(a[mt][3]),
                          "r"(b[nt][0]), "r"(b[nt][1]));
        }
        __syncthreads();
        st ^= 1;
    }

    // epilogue: bf16 featb stores + fused el2/er2 (warp tile = one head)
    #pragma unroll
    for (int mt = 0; mt < 4; mt++) {
        int gr0 = rowBase + mw + mt * 16 + g;
        int gr1 = gr0 + 8;
        #pragma unroll
        for (int nt = 0; nt < 4; nt++) {
            int col = colBase + nw + nt * 8 + tig * 2;
            if (gr0 < Nn) {
                __nv_bfloat162 p = __floats2bfloat162_rn(cf[mt][nt][0], cf[mt][nt][1]);
                *(__nv_bfloat162*)&g_featb[gr0 * F + col] = p;
            }
            if (gr1 < Nn) {
                __nv_bfloat162 p = __floats2bfloat162_rn(cf[mt][nt][2], cf[mt][nt][3]);
                *(__nv_bfloat162*)&g_featb[gr1 * F + col] = p;
            }
        }
    }
    int hid = (colBase + nw) >> 5;
    float alv[4][2], arv[4][2];
    #pragma unroll
    for (int nt = 0; nt < 4; nt++) {
        int col = colBase + nw + nt * 8 + tig * 2;
        alv[nt][0] = al2[col]; alv[nt][1] = al2[col + 1];
        arv[nt][0] = ar2[col]; arv[nt][1] = ar2[col + 1];
    }
    #pragma unroll
    for (int mt = 0; mt < 4; mt++) {
        float el0 = 0.f, el1v = 0.f, er0 = 0.f, er1v = 0.f;
        #pragma unroll
        for (int nt = 0; nt < 4; nt++) {
            el0  += cf[mt][nt][0] * alv[nt][0] + cf[mt][nt][1] * alv[nt][1];
            el1v += cf[mt][nt][2] * alv[nt][0] + cf[mt][nt][3] * alv[nt][1];
            er0  += cf[mt][nt][0] * arv[nt][0] + cf[mt][nt][1] * arv[nt][1];
            er1v += cf[mt][nt][2] * arv[nt][0] + cf[mt][nt][3] * arv[nt][1];
        }
        el0  += __shfl_xor_sync(0xffffffffu, el0, 1);  el0  += __shfl_xor_sync(0xffffffffu, el0, 2);
        el1v += __shfl_xor_sync(0xffffffffu, el1v, 1); el1v += __shfl_xor_sync(0xffffffffu, el1v, 2);
        er0  += __shfl_xor_sync(0xffffffffu, er0, 1);  er0  += __shfl_xor_sync(0xffffffffu, er0, 2);
        er1v += __shfl_xor_sync(0xffffffffu, er1v, 1); er1v += __shfl_xor_sync(0xffffffffu, er1v, 2);
        if (tig == 0) {
            int gr0 = rowBase + mw + mt * 16 + g;
            int gr1 = gr0 + 8;
            if (gr0 < Nn) { g_el[gr0 * Hh + hid] = el0;  g_er[gr0 * Hh + hid] = er0; }
            if (gr1 < Nn) { g_el[gr1 * Hh + hid] = el1v; g_er[gr1 * Hh + hid] = er1v; }
        }
    }
}

// ---------------- MLP head ----------------
__global__ void mlp_kernel(const float* __restrict__ Wp1, const float* __restrict__ bp1,
                           const float* __restrict__ gamma, const float* __restrict__ beta,
                           const float* __restrict__ rm, const float* __restrict__ rv,
                           const float* __restrict__ Wp2, const float* __restrict__ bp2,
                           float* __restrict__ out) {
    int g = blockIdx.x;
    int t = threadIdx.x;      // 0..127
    __shared__ float gv[2 * Dd];
    __shared__ float red[HID];
    if (t < Dd) gv[t] = g_gsum[g * Dd + t];
    else if (t < 2 * Dd) {
        float mv = g_gmax[g * Dd + (t - Dd)];
        gv[t] = isfinite(mv) ? mv : 0.f;
    }
    __syncthreads();
    float acc = bp1[t];
    #pragma unroll
    for (int k = 0; k < 2 * Dd; k++) acc = fmaf(gv[k], Wp1[k * HID + t], acc);
    acc = fmaxf(acc, 0.f);
    acc = (acc - rm[t]) * rsqrtf(rv[t] + BN_EPS) * gamma[t] + beta[t];
    red[t] = acc * Wp2[t];
    __syncthreads();
    for (int s = 64; s > 0; s >>= 1) {
        if (t < s) red[t] += red[t + s];
        __syncthreads();
    }
    if (t == 0) out[g] = red[0] + bp2[0];
}

// ---------------- launch ----------------
extern "C" void kernel_launch(void* const* d_in, const int* in_sizes, int n_in,
                              void* d_out, int out_size) {
    const float* x     = (const float*)d_in[0];
    const int*   src   = (const int*)  d_in[1];
    const int*   dst   = (const int*)  d_in[2];
    const int*   gids  = (const int*)  d_in[3];
    const float* W1    = (const float*)d_in[4];
    const float* al1   = (const float*)d_in[5];
    const float* ar1   = (const float*)d_in[6];
    const float* b1    = (const float*)d_in[7];
    const float* resW1 = (const float*)d_in[8];
    const float* W2    = (const float*)d_in[9];
    const float* al2   = (const float*)d_in[10];
    const float* ar2   = (const float*)d_in[11];
    const float* b2    = (const float*)d_in[12];
    const float* Ww    = (const float*)d_in[13];
    const float* bw    = (const float*)d_in[14];
    const float* Wp1   = (const float*)d_in[15];
    const float* bp1   = (const float*)d_in[16];
    const float* gamma = (const float*)d_in[17];
    const float* beta  = (const float*)d_in[18];
    const float* rm    = (const float*)d_in[19];
    const float* rv    = (const float*)d_in[20];
    const float* Wp2   = (const float*)d_in[21];
    const float* bp2   = (const float*)d_in[22];
    float* out = (float*)d_out;

    float* ph1; cudaGetSymbolAddress((void**)&ph1, g_h1);

    static cudaStream_t s2 = nullptr;
    static cudaEvent_t e1 = nullptr, e2 = nullptr;
    if (!s2) {
        cudaStreamCreateWithFlags(&s2, cudaStreamNonBlocking);
        cudaEventCreateWithFlags(&e1, cudaEventDisableTiming);
        cudaEventCreateWithFlags(&e2, cudaEventDisableTiming);
        cudaFuncSetAttribute(gemm2_tc_kernel,
                             cudaFuncAttributeMaxDynamicSharedMemorySize, SMEM_GEMM);
    }

    cudaEventRecord(e1, 0);
    cudaStreamWaitEvent(s2, e1, 0);

    // ===== side stream: CSR build (self-clearing cnt; fills folded into scan_p2) =====
    hist_kernel<<<(Ee + 255) / 256, 256, 0, s2>>>(dst);
    scan_p1_kernel<<<NSCAN, 256, 0, s2>>>();
    scan_p2_kernel<<<NSCAN, 256, 0, s2>>>();
    scatter_kernel<<<(Ee + 255) / 256, 256, 0, s2>>>(src, dst);
    cudaEventRecord(e2, s2);

    // ===== main stream: layer 1 tensor-core projection (overlaps CSR build) =====
    {
        dim3 grid(4, (Nn + 127) / 128);
        node1_tc_kernel<<<grid, 256>>>(x, W1, resW1, b1, al1, ar1);
    }

    cudaStreamWaitEvent(0, e2, 0);
    agg1_kernel<<<Nn / 8, 256>>>();

    // ===== layer 2 (pipelined tf32 GEMM) =====
    {
        dim3 grid(F / TBN, (Nn + TBM - 1) / TBM);
        gemm2_tc_kernel<<<grid, 256, SMEM_GEMM>>>(ph1, W2, al2, ar2);
    }
    agg2_kernel<<<Nn / 8, 256>>>(b2, gids, Ww, bw);

    // ===== MLP =====
    mlp_kernel<<<Gg, HID>>>(Wp1, bp1, gamma, beta, rm, rv, Wp2, bp2, out);
}